// round 5
// baseline (speedup 1.0000x reference)
#include <cuda_runtime.h>
#include <cstdint>

// Problem: AveragePrecision_4690104287320
// output: (16,3,128,128,85) f32 -> 786,432 rows of 85 floats
// anchors: unused. targets: (16,50,5) f32 -> identity copy.
// Out: pred_out (786432 x 7 f32) then target copy (4000 f32).

#define CONF_THRESHOLD 0.25f

constexpr int ROWS    = 128;                 // rows (threads) per tile
constexpr int VROW    = 85;
constexpr int SMEM_F  = ROWS * VROW;         // 10880 floats per tile
constexpr int TILE_B  = SMEM_F * 4;          // 43520 bytes
constexpr int OUT_F   = ROWS * 7;            // 896 floats
constexpr int OUT_B   = OUT_F * 4;           // 3584 bytes
constexpr int DEPTH   = 4;                   // input ring depth
constexpr int DSMEM_B = DEPTH * TILE_B + 2 * OUT_B;   // 181,248 B

__device__ __forceinline__ uint32_t smem_u32(const void* p) {
    uint32_t a;
    asm("{ .reg .u64 t; cvta.to.shared.u64 t, %1; cvt.u32.u64 %0, t; }" : "=r"(a) : "l"(p));
    return a;
}

__device__ __forceinline__ void mbar_wait(uint32_t mb, int phase) {
    uint32_t done;
    asm volatile(
        "{\n\t.reg .pred p;\n\t"
        "mbarrier.try_wait.parity.acquire.cta.shared::cta.b64 p, [%1], %2;\n\t"
        "selp.b32 %0, 1, 0, p;\n\t}"
        : "=r"(done) : "r"(mb), "r"(phase) : "memory");
    if (!done) {
        asm volatile(
            "{\n\t.reg .pred P1;\n\t"
            "WAIT_LOOP_%=:\n\t"
            "mbarrier.try_wait.parity.acquire.cta.shared::cta.b64 P1, [%0], %1, 0x989680;\n\t"
            "@P1 bra.uni WAIT_DONE_%=;\n\t"
            "bra.uni WAIT_LOOP_%=;\n\t"
            "WAIT_DONE_%=:\n\t}"
            :: "r"(mb), "r"(phase) : "memory");
    }
}

__device__ __forceinline__ void issue_prefetch(uint32_t mb, float* dst_smem,
                                               const float* src) {
    asm volatile("mbarrier.arrive.expect_tx.shared.b64 _, [%0], %1;"
                 :: "r"(mb), "r"((uint32_t)TILE_B) : "memory");
    asm volatile("cp.async.bulk.shared::cta.global.mbarrier::complete_tx::bytes "
                 "[%0], [%1], %2, [%3];"
                 :: "r"(smem_u32(dst_smem)), "l"(src),
                    "r"((uint32_t)TILE_B), "r"(mb) : "memory");
}

__global__ void __launch_bounds__(ROWS)
yolo_fuse_kernel(const float* __restrict__ pred,
                 float* __restrict__ out,
                 const float4* __restrict__ targ4,
                 float4* __restrict__ targ_out4,
                 int ntiles)
{
    extern __shared__ __align__(16) float smem[];   // DEPTH input tiles + 2 out staging
    __shared__ __align__(8) uint64_t mbar[DEPTH];

    const int tid  = threadIdx.x;
    const int grid = gridDim.x;
    const int t0   = blockIdx.x;
    float* stg = smem + DEPTH * SMEM_F;             // 2 x OUT_F floats

    if (tid == 0) {
        #pragma unroll
        for (int k = 0; k < DEPTH; k++) {
            asm volatile("mbarrier.init.shared.b64 [%0], %1;"
                         :: "r"(smem_u32(&mbar[k])), "r"(1) : "memory");
        }
    }
    __syncthreads();

    // fused targets copy (4000 floats = 1000 float4; blocks 0..7 x 125)
    if (blockIdx.x < 8 && tid < 125) {
        int idx = (int)blockIdx.x * 125 + tid;
        targ_out4[idx] = targ4[idx];
    }

    // prologue: fill the ring (up to DEPTH tiles in flight)
    if (tid == 0) {
        #pragma unroll
        for (int k = 0; k < DEPTH; k++) {
            int tk = t0 + k * grid;
            if (tk < ntiles)
                issue_prefetch(smem_u32(&mbar[k]), smem + k * SMEM_F,
                               pred + (long long)tk * SMEM_F);
        }
    }

    int i = 0;
    for (int t = t0; t < ntiles; t += grid, i++) {
        const int b = i & (DEPTH - 1);
        float* buf = smem + b * SMEM_F;

        // wait for current tile (parity = use-count LSB)
        mbar_wait(smem_u32(&mbar[b]), (i >> 2) & 1);

        // ---- thread-per-row scan (stride-85: bank-conflict-free) ----
        const float* row = buf + tid * VROW;
        const float b0 = row[0], b1v = row[1], b2 = row[2], b3 = row[3];
        const float obj = row[4];

        float m0 = row[5], m1 = row[6], m2 = row[7], m3 = row[8];
        int   i0 = 0,      i1 = 1,      i2 = 2,      i3 = 3;
        #pragma unroll
        for (int k = 1; k < 20; k++) {
            const float v0 = row[5 + 4 * k];
            const float v1 = row[6 + 4 * k];
            const float v2 = row[7 + 4 * k];
            const float v3 = row[8 + 4 * k];
            if (v0 > m0) { m0 = v0; i0 = 4 * k;     }
            if (v1 > m1) { m1 = v1; i1 = 4 * k + 1; }
            if (v2 > m2) { m2 = v2; i2 = 4 * k + 2; }
            if (v3 > m3) { m3 = v3; i3 = 4 * k + 3; }
        }
        float best = m0; int bidx = i0;
        if (m1 > best || (m1 == best && i1 < bidx)) { best = m1; bidx = i1; }
        if (m2 > best || (m2 == best && i2 < bidx)) { best = m2; bidx = i2; }
        if (m3 > best || (m3 == best && i3 < bidx)) { best = m3; bidx = i3; }

        const float conf = best * obj;
        const bool  keep = conf > CONF_THRESHOLD;

        float r[7];
        r[0] = keep ? b0  : 0.0f;
        r[1] = keep ? b1v : 0.0f;
        r[2] = keep ? b2  : 0.0f;
        r[3] = keep ? b3  : 0.0f;
        r[4] = keep ? obj : 0.0f;
        r[5] = keep ? (float)bidx : 0.0f;
        r[6] = keep ? conf : 0.0f;

        // staging buffer (ping-pong): ensure the store 2 iters ago finished reading
        if (tid == 0) {
            asm volatile("cp.async.bulk.wait_group.read 1;" ::: "memory");
        }
        __syncthreads();                 // also: all compute reads of buf done

        float* sout = stg + (i & 1) * OUT_F;
        #pragma unroll
        for (int j = 0; j < 7; j++) sout[tid * 7 + j] = r[j];   // stride-7: conflict-free
        __syncthreads();

        if (tid == 0) {
            // bulk store 3584 B shared -> global
            asm volatile("fence.proxy.async.shared::cta;" ::: "memory");
            asm volatile("cp.async.bulk.global.shared::cta.bulk_group [%0], [%1], %2;"
                         :: "l"(out + (long long)t * OUT_F), "r"(smem_u32(sout)),
                            "r"((uint32_t)OUT_B) : "memory");
            asm volatile("cp.async.bulk.commit_group;" ::: "memory");

            // refill this ring slot with the tile DEPTH strides ahead
            const long long nt = (long long)t + (long long)DEPTH * grid;
            if (nt < ntiles)
                issue_prefetch(smem_u32(&mbar[b]), buf, pred + nt * SMEM_F);
        }
    }

    // drain outstanding bulk stores before exit
    if (tid == 0) {
        asm volatile("cp.async.bulk.wait_group 0;" ::: "memory");
    }
}

extern "C" void kernel_launch(void* const* d_in, const int* in_sizes, int n_in,
                              void* d_out, int out_size)
{
    const float* output  = (const float*)d_in[0];   // (16,3,128,128,85)
    const float* targets = (const float*)d_in[2];   // (16,50,5)

    float* out = (float*)d_out;

    const int nrows  = in_sizes[0] / VROW;          // 786432 (multiple of 128)
    const int ntiles = nrows / ROWS;                // 6144
    float* targ_out = out + (long long)nrows * 7;

    static int sm_count = 0;
    if (sm_count == 0) {
        cudaDeviceGetAttribute(&sm_count, cudaDevAttrMultiProcessorCount, 0);
        if (sm_count <= 0) sm_count = 148;
        cudaFuncSetAttribute(yolo_fuse_kernel,
                             cudaFuncAttributeMaxDynamicSharedMemorySize, DSMEM_B);
    }

    const int grid = (ntiles < sm_count) ? ntiles : sm_count;
    yolo_fuse_kernel<<<grid, ROWS, DSMEM_B>>>(output, out,
                                              (const float4*)targets,
                                              (float4*)targ_out, ntiles);
}

// round 6
// speedup vs baseline: 1.0577x; 1.0577x over previous
#include <cuda_runtime.h>
#include <cstdint>

// Problem: AveragePrecision_4690104287320
// output: (16,3,128,128,85) f32 -> 786,432 rows of 85 floats
// anchors: unused. targets: (16,50,5) f32 -> identity copy.
// Out: pred_out (786432 x 7 f32) then target copy (4000 f32).

#define CONF_THRESHOLD 0.25f

constexpr int ROWS   = 64;                  // rows per tile = threads per block
constexpr int VROW   = 85;
constexpr int SMEM_F = ROWS * VROW;         // 5440 floats
constexpr int TILE_B = SMEM_F * 4;          // 21760 bytes (16B multiple)
constexpr int OUT_F  = ROWS * 7;            // 448 floats
constexpr int OUT_V4 = OUT_F / 4;           // 112 float4

__device__ __forceinline__ uint32_t smem_u32(const void* p) {
    uint32_t a;
    asm("{ .reg .u64 t; cvta.to.shared.u64 t, %1; cvt.u32.u64 %0, t; }" : "=r"(a) : "l"(p));
    return a;
}

__global__ void __launch_bounds__(ROWS)
yolo_fuse_kernel(const float* __restrict__ pred,
                 float4* __restrict__ out4,
                 const float4* __restrict__ targ4,
                 float4* __restrict__ targ_out4)
{
    __shared__ __align__(16) float smem[SMEM_F];
    __shared__ __align__(8) uint64_t mbar;

    const int tid = threadIdx.x;
    const long long blk = blockIdx.x;
    const uint32_t mb = smem_u32(&mbar);

    if (tid == 0) {
        asm volatile("mbarrier.init.shared.b64 [%0], %1;" :: "r"(mb), "r"(1) : "memory");
    }
    __syncthreads();

    // ---- one bulk DMA: 21,760 B global -> shared ----
    if (tid == 0) {
        asm volatile("mbarrier.arrive.expect_tx.shared.b64 _, [%0], %1;"
                     :: "r"(mb), "r"((uint32_t)TILE_B) : "memory");
        const float* src = pred + blk * (long long)SMEM_F;
        asm volatile("cp.async.bulk.shared::cta.global.mbarrier::complete_tx::bytes "
                     "[%0], [%1], %2, [%3];"
                     :: "r"(smem_u32(smem)), "l"(src), "r"((uint32_t)TILE_B), "r"(mb)
                     : "memory");
    }

    // ---- fused targets copy (1000 float4 over blocks 0..7, 2 chunks/thread) ----
    if (blk < 8) {
        int k0 = tid;           // 0..63
        int k1 = tid + 64;      // 64..127
        if (k0 < 125) targ_out4[(int)blk * 125 + k0] = targ4[(int)blk * 125 + k0];
        if (k1 < 125) targ_out4[(int)blk * 125 + k1] = targ4[(int)blk * 125 + k1];
    }

    // ---- wait for tile ----
    {
        uint32_t done;
        asm volatile(
            "{\n\t.reg .pred p;\n\t"
            "mbarrier.try_wait.parity.acquire.cta.shared::cta.b64 p, [%1], %2;\n\t"
            "selp.b32 %0, 1, 0, p;\n\t}"
            : "=r"(done) : "r"(mb), "r"(0) : "memory");
        if (!done) {
            asm volatile(
                "{\n\t.reg .pred P1;\n\t"
                "WAIT_LOOP_%=:\n\t"
                "mbarrier.try_wait.parity.acquire.cta.shared::cta.b64 P1, [%0], %1, 0x989680;\n\t"
                "@P1 bra.uni WAIT_DONE_%=;\n\t"
                "bra.uni WAIT_LOOP_%=;\n\t"
                "WAIT_DONE_%=:\n\t}"
                :: "r"(mb), "r"(0) : "memory");
        }
    }

    // ---- thread-per-row scan (stride-85 floats: bank-conflict-free) ----
    const float* row = smem + tid * VROW;
    const float b0 = row[0], b1 = row[1], b2 = row[2], b3 = row[3];
    const float obj = row[4];

    float m0 = row[5], m1 = row[6], m2 = row[7], m3 = row[8];
    int   i0 = 0,      i1 = 1,      i2 = 2,      i3 = 3;
    #pragma unroll
    for (int k = 1; k < 20; k++) {
        const float v0 = row[5 + 4 * k];
        const float v1 = row[6 + 4 * k];
        const float v2 = row[7 + 4 * k];
        const float v3 = row[8 + 4 * k];
        if (v0 > m0) { m0 = v0; i0 = 4 * k;     }
        if (v1 > m1) { m1 = v1; i1 = 4 * k + 1; }
        if (v2 > m2) { m2 = v2; i2 = 4 * k + 2; }
        if (v3 > m3) { m3 = v3; i3 = 4 * k + 3; }
    }
    float best = m0; int bidx = i0;
    if (m1 > best || (m1 == best && i1 < bidx)) { best = m1; bidx = i1; }
    if (m2 > best || (m2 == best && i2 < bidx)) { best = m2; bidx = i2; }
    if (m3 > best || (m3 == best && i3 < bidx)) { best = m3; bidx = i3; }

    const float conf = best * obj;
    const bool  keep = conf > CONF_THRESHOLD;

    float r[7];
    r[0] = keep ? b0 : 0.0f;
    r[1] = keep ? b1 : 0.0f;
    r[2] = keep ? b2 : 0.0f;
    r[3] = keep ? b3 : 0.0f;
    r[4] = keep ? obj : 0.0f;
    r[5] = keep ? (float)bidx : 0.0f;
    r[6] = keep ? conf : 0.0f;

    // ---- stage results (stride-7 over 64 threads: conflict-free), coalesced f4 store ----
    __syncthreads();   // all reads of row data done before overwrite
    #pragma unroll
    for (int j = 0; j < 7; j++) smem[tid * 7 + j] = r[j];
    __syncthreads();

    const float4* s4 = reinterpret_cast<const float4*>(smem);
    float4* dst = out4 + blk * OUT_V4;
    #pragma unroll
    for (int i = 0; i < OUT_V4 / ROWS + 1; i++) {
        int idx = tid + i * ROWS;
        if (idx < OUT_V4) __stcs(dst + idx, s4[idx]);
    }
}

extern "C" void kernel_launch(void* const* d_in, const int* in_sizes, int n_in,
                              void* d_out, int out_size)
{
    const float* output  = (const float*)d_in[0];   // (16,3,128,128,85)
    const float* targets = (const float*)d_in[2];   // (16,50,5)

    float* out = (float*)d_out;

    const int nrows = in_sizes[0] / VROW;           // 786432 (multiple of 64)
    float* targ_out = out + (long long)nrows * 7;

    const int grid = nrows / ROWS;                  // 12288 blocks
    yolo_fuse_kernel<<<grid, ROWS>>>(output, (float4*)out,
                                     (const float4*)targets, (float4*)targ_out);
}

// round 7
// speedup vs baseline: 1.0681x; 1.0098x over previous
#include <cuda_runtime.h>
#include <cstdint>

// Problem: AveragePrecision_4690104287320
// output: (16,3,128,128,85) f32 -> 786,432 rows of 85 floats
// anchors: unused. targets: (16,50,5) f32 -> identity copy.
// Out: pred_out (786432 x 7 f32) then target copy (4000 f32).

#define CONF_THRESHOLD 0.25f

constexpr int HROWS  = 64;                   // rows per half-tile
constexpr int VROW   = 85;
constexpr int HSMEM_F = HROWS * VROW;        // 5440 floats per half
constexpr int HTILE_B = HSMEM_F * 4;         // 21760 bytes per half
constexpr int HOUT_F  = HROWS * 7;           // 448 floats per half
constexpr int HOUT_V4 = HOUT_F / 4;          // 112 float4 per half

__device__ __forceinline__ uint32_t smem_u32(const void* p) {
    uint32_t a;
    asm("{ .reg .u64 t; cvta.to.shared.u64 t, %1; cvt.u32.u64 %0, t; }" : "=r"(a) : "l"(p));
    return a;
}

__device__ __forceinline__ void mbar_wait0(uint32_t mb) {
    uint32_t done;
    asm volatile(
        "{\n\t.reg .pred p;\n\t"
        "mbarrier.try_wait.parity.acquire.cta.shared::cta.b64 p, [%1], %2;\n\t"
        "selp.b32 %0, 1, 0, p;\n\t}"
        : "=r"(done) : "r"(mb), "r"(0) : "memory");
    if (!done) {
        asm volatile(
            "{\n\t.reg .pred P1;\n\t"
            "WAIT_LOOP_%=:\n\t"
            "mbarrier.try_wait.parity.acquire.cta.shared::cta.b64 P1, [%0], %1, 0x989680;\n\t"
            "@P1 bra.uni WAIT_DONE_%=;\n\t"
            "bra.uni WAIT_LOOP_%=;\n\t"
            "WAIT_DONE_%=:\n\t}"
            :: "r"(mb), "r"(0) : "memory");
    }
}

__global__ void __launch_bounds__(128)
yolo_fuse_kernel(const float* __restrict__ pred,
                 float4* __restrict__ out4,
                 const float4* __restrict__ targ4,
                 float4* __restrict__ targ_out4)
{
    __shared__ __align__(16) float smem[2 * HSMEM_F];
    __shared__ __align__(8) uint64_t mbar[2];

    const int tid  = threadIdx.x;
    const int half = tid >> 6;               // 0 or 1
    const int lid  = tid & 63;               // row within half-tile
    const long long blk = blockIdx.x;
    const uint32_t mb0 = smem_u32(&mbar[0]);
    const uint32_t mb1 = smem_u32(&mbar[1]);

    if (tid == 0) {
        asm volatile("mbarrier.init.shared.b64 [%0], %1;" :: "r"(mb0), "r"(1) : "memory");
        asm volatile("mbarrier.init.shared.b64 [%0], %1;" :: "r"(mb1), "r"(1) : "memory");
    }
    __syncthreads();

    // ---- issue BOTH half-tile DMAs immediately, back-to-back ----
    if (tid == 0) {
        const float* src = pred + blk * (long long)(2 * HSMEM_F);
        asm volatile("mbarrier.arrive.expect_tx.shared.b64 _, [%0], %1;"
                     :: "r"(mb0), "r"((uint32_t)HTILE_B) : "memory");
        asm volatile("cp.async.bulk.shared::cta.global.mbarrier::complete_tx::bytes "
                     "[%0], [%1], %2, [%3];"
                     :: "r"(smem_u32(smem)), "l"(src),
                        "r"((uint32_t)HTILE_B), "r"(mb0) : "memory");
        asm volatile("mbarrier.arrive.expect_tx.shared.b64 _, [%0], %1;"
                     :: "r"(mb1), "r"((uint32_t)HTILE_B) : "memory");
        asm volatile("cp.async.bulk.shared::cta.global.mbarrier::complete_tx::bytes "
                     "[%0], [%1], %2, [%3];"
                     :: "r"(smem_u32(smem + HSMEM_F)), "l"(src + HSMEM_F),
                        "r"((uint32_t)HTILE_B), "r"(mb1) : "memory");
    }

    // ---- fused targets copy (1000 float4 over blocks 0..7) ----
    if (blk < 8 && tid < 125) {
        int idx = (int)blk * 125 + tid;
        targ_out4[idx] = targ4[idx];
    }

    // ---- each half proceeds independently from here ----
    float* hbuf = smem + half * HSMEM_F;
    mbar_wait0(half ? mb1 : mb0);

    // thread-per-row scan (stride-85 floats: bank-conflict-free)
    const float* row = hbuf + lid * VROW;
    const float b0 = row[0], b1 = row[1], b2 = row[2], b3 = row[3];
    const float obj = row[4];

    float m0 = row[5], m1 = row[6], m2 = row[7], m3 = row[8];
    int   i0 = 0,      i1 = 1,      i2 = 2,      i3 = 3;
    #pragma unroll
    for (int k = 1; k < 20; k++) {
        const float v0 = row[5 + 4 * k];
        const float v1 = row[6 + 4 * k];
        const float v2 = row[7 + 4 * k];
        const float v3 = row[8 + 4 * k];
        if (v0 > m0) { m0 = v0; i0 = 4 * k;     }
        if (v1 > m1) { m1 = v1; i1 = 4 * k + 1; }
        if (v2 > m2) { m2 = v2; i2 = 4 * k + 2; }
        if (v3 > m3) { m3 = v3; i3 = 4 * k + 3; }
    }
    float best = m0; int bidx = i0;
    if (m1 > best || (m1 == best && i1 < bidx)) { best = m1; bidx = i1; }
    if (m2 > best || (m2 == best && i2 < bidx)) { best = m2; bidx = i2; }
    if (m3 > best || (m3 == best && i3 < bidx)) { best = m3; bidx = i3; }

    const float conf = best * obj;
    const bool  keep = conf > CONF_THRESHOLD;

    float r[7];
    r[0] = keep ? b0 : 0.0f;
    r[1] = keep ? b1 : 0.0f;
    r[2] = keep ? b2 : 0.0f;
    r[3] = keep ? b3 : 0.0f;
    r[4] = keep ? obj : 0.0f;
    r[5] = keep ? (float)bidx : 0.0f;
    r[6] = keep ? conf : 0.0f;

    // half-scope barrier: all 64 threads of this half done reading their rows
    asm volatile("bar.sync %0, 64;" :: "r"(half + 1) : "memory");

    #pragma unroll
    for (int j = 0; j < 7; j++) hbuf[lid * 7 + j] = r[j];   // stride-7: conflict-free

    asm volatile("bar.sync %0, 64;" :: "r"(half + 1) : "memory");

    // coalesced float4 store of this half's 448 floats
    const float4* s4 = reinterpret_cast<const float4*>(hbuf);
    float4* dst = out4 + (blk * 2 + half) * HOUT_V4;
    __stcs(dst + lid, s4[lid]);                 // idx 0..63
    if (lid < HOUT_V4 - HROWS)                  // idx 64..111
        __stcs(dst + lid + HROWS, s4[lid + HROWS]);
}

extern "C" void kernel_launch(void* const* d_in, const int* in_sizes, int n_in,
                              void* d_out, int out_size)
{
    const float* output  = (const float*)d_in[0];   // (16,3,128,128,85)
    const float* targets = (const float*)d_in[2];   // (16,50,5)

    float* out = (float*)d_out;

    const int nrows = in_sizes[0] / VROW;           // 786432 (multiple of 128)
    float* targ_out = out + (long long)nrows * 7;

    const int grid = nrows / 128;                   // 6144 blocks (2 half-tiles each)
    yolo_fuse_kernel<<<grid, 128>>>(output, (float4*)out,
                                    (const float4*)targets, (float4*)targ_out);
}

// round 8
// speedup vs baseline: 1.0689x; 1.0007x over previous
#include <cuda_runtime.h>
#include <cstdint>

// Problem: AveragePrecision_4690104287320
// output: (16,3,128,128,85) f32 -> 786,432 rows of 85 floats
// anchors: unused. targets: (16,50,5) f32 -> identity copy.
// Out: pred_out (786432 x 7 f32) then target copy (4000 f32).

#define CONF_THRESHOLD 0.25f

constexpr int ROWS   = 64;                  // rows per tile = threads per block
constexpr int VROW   = 85;
constexpr int SMEM_F = ROWS * VROW;         // 5440 floats
constexpr int TILE_B = SMEM_F * 4;          // 21760 bytes (16B multiple)
constexpr int OUT_F  = ROWS * 7;            // 448 floats
constexpr int OUT_V4 = OUT_F / 4;           // 112 float4

__device__ __forceinline__ uint32_t smem_u32(const void* p) {
    uint32_t a;
    asm("{ .reg .u64 t; cvta.to.shared.u64 t, %1; cvt.u32.u64 %0, t; }" : "=r"(a) : "l"(p));
    return a;
}

__global__ void __launch_bounds__(ROWS)
yolo_fuse_kernel(const float* __restrict__ pred,
                 float4* __restrict__ out4,
                 const float4* __restrict__ targ4,
                 float4* __restrict__ targ_out4)
{
    __shared__ __align__(16) float smem[SMEM_F];
    __shared__ __align__(8) uint64_t mbar;

    const int tid = threadIdx.x;
    const long long blk = blockIdx.x;
    const uint32_t mb = smem_u32(&mbar);

    // ---- tid0: init mbarrier and IMMEDIATELY issue the bulk DMA (before any
    //      block-wide sync). Program order + fence.mbarrier_init orders the
    //      init against the async-proxy TMA use within this thread. ----
    if (tid == 0) {
        asm volatile("mbarrier.init.shared.b64 [%0], %1;" :: "r"(mb), "r"(1) : "memory");
        asm volatile("fence.mbarrier_init.release.cluster;" ::: "memory");
        asm volatile("mbarrier.arrive.expect_tx.shared.b64 _, [%0], %1;"
                     :: "r"(mb), "r"((uint32_t)TILE_B) : "memory");
        const float* src = pred + blk * (long long)SMEM_F;
        asm volatile("cp.async.bulk.shared::cta.global.mbarrier::complete_tx::bytes "
                     "[%0], [%1], %2, [%3];"
                     :: "r"(smem_u32(smem)), "l"(src), "r"((uint32_t)TILE_B), "r"(mb)
                     : "memory");
    }

    // ---- fused targets copy (1000 float4 over blocks 0..7, 2 chunks/thread) ----
    if (blk < 8) {
        int k0 = tid;           // 0..63
        int k1 = tid + 64;      // 64..127
        if (k0 < 125) targ_out4[(int)blk * 125 + k0] = targ4[(int)blk * 125 + k0];
        if (k1 < 125) targ_out4[(int)blk * 125 + k1] = targ4[(int)blk * 125 + k1];
    }

    // all threads must observe the initialized mbarrier before waiting on it
    __syncthreads();

    // ---- wait for tile ----
    {
        uint32_t done;
        asm volatile(
            "{\n\t.reg .pred p;\n\t"
            "mbarrier.try_wait.parity.acquire.cta.shared::cta.b64 p, [%1], %2;\n\t"
            "selp.b32 %0, 1, 0, p;\n\t}"
            : "=r"(done) : "r"(mb), "r"(0) : "memory");
        if (!done) {
            asm volatile(
                "{\n\t.reg .pred P1;\n\t"
                "WAIT_LOOP_%=:\n\t"
                "mbarrier.try_wait.parity.acquire.cta.shared::cta.b64 P1, [%0], %1, 0x989680;\n\t"
                "@P1 bra.uni WAIT_DONE_%=;\n\t"
                "bra.uni WAIT_LOOP_%=;\n\t"
                "WAIT_DONE_%=:\n\t}"
                :: "r"(mb), "r"(0) : "memory");
        }
    }

    // ---- thread-per-row scan (stride-85 floats: bank-conflict-free) ----
    const float* row = smem + tid * VROW;
    const float b0 = row[0], b1 = row[1], b2 = row[2], b3 = row[3];
    const float obj = row[4];

    float m0 = row[5], m1 = row[6], m2 = row[7], m3 = row[8];
    int   i0 = 0,      i1 = 1,      i2 = 2,      i3 = 3;
    #pragma unroll
    for (int k = 1; k < 20; k++) {
        const float v0 = row[5 + 4 * k];
        const float v1 = row[6 + 4 * k];
        const float v2 = row[7 + 4 * k];
        const float v3 = row[8 + 4 * k];
        if (v0 > m0) { m0 = v0; i0 = 4 * k;     }
        if (v1 > m1) { m1 = v1; i1 = 4 * k + 1; }
        if (v2 > m2) { m2 = v2; i2 = 4 * k + 2; }
        if (v3 > m3) { m3 = v3; i3 = 4 * k + 3; }
    }
    float best = m0; int bidx = i0;
    if (m1 > best || (m1 == best && i1 < bidx)) { best = m1; bidx = i1; }
    if (m2 > best || (m2 == best && i2 < bidx)) { best = m2; bidx = i2; }
    if (m3 > best || (m3 == best && i3 < bidx)) { best = m3; bidx = i3; }

    const float conf = best * obj;
    const bool  keep = conf > CONF_THRESHOLD;

    float r[7];
    r[0] = keep ? b0 : 0.0f;
    r[1] = keep ? b1 : 0.0f;
    r[2] = keep ? b2 : 0.0f;
    r[3] = keep ? b3 : 0.0f;
    r[4] = keep ? obj : 0.0f;
    r[5] = keep ? (float)bidx : 0.0f;
    r[6] = keep ? conf : 0.0f;

    // ---- stage results (stride-7 over 64 threads: conflict-free), coalesced f4 store ----
    __syncthreads();   // all reads of row data done before overwrite
    #pragma unroll
    for (int j = 0; j < 7; j++) smem[tid * 7 + j] = r[j];
    __syncthreads();

    const float4* s4 = reinterpret_cast<const float4*>(smem);
    float4* dst = out4 + blk * OUT_V4;
    __stcs(dst + tid, s4[tid]);                    // idx 0..63
    if (tid < OUT_V4 - ROWS)                       // idx 64..111
        __stcs(dst + tid + ROWS, s4[tid + ROWS]);
}

extern "C" void kernel_launch(void* const* d_in, const int* in_sizes, int n_in,
                              void* d_out, int out_size)
{
    const float* output  = (const float*)d_in[0];   // (16,3,128,128,85)
    const float* targets = (const float*)d_in[2];   // (16,50,5)

    float* out = (float*)d_out;

    const int nrows = in_sizes[0] / VROW;           // 786432 (multiple of 64)
    float* targ_out = out + (long long)nrows * 7;

    const int grid = nrows / ROWS;                  // 12288 blocks
    yolo_fuse_kernel<<<grid, ROWS>>>(output, (float4*)out,
                                     (const float4*)targets, (float4*)targ_out);
}